// round 8
// baseline (speedup 1.0000x reference)
#include <cuda_runtime.h>
#include <math.h>

// ---------------- problem constants ----------------
#define B_ 256
#define T_ 500
#define I_ 8
#define H_ 1024
#define O_ 8
#define ALPHA_ 0.2f
#define NSTD_ 0.05f

// ---------------- geometry ----------------
#define GRID_ 128          // 16 j-tiles x 8 batch-tiles, all co-resident
#define NTHR 512           // 16 warps; warp owns 4 j-columns; lane owns 1 batch elem
#define NWARP 16
#define BM 32              // batch tile (= warp width)
#define BN 64              // j tile (16 warps x 4 cols)
#define COLS_W 4
#define KSEG 256
#define NSEG 4
#define JT_QCAP 3584       // quads per j-tile (avg need ~2950 incl. mult-of-4 pad)

// ---------------- smem layout (byte offsets) ----------------
#define LIST_OFF  0
#define LIST_BYTES (JT_QCAP * 32)                 // 114688
#define TAB_OFF   (LIST_OFF + LIST_BYTES)
#define TAB_BYTES (NWARP * NSEG * 8)              // 512 (int2 per (group,seg))
#define RBUF_OFF  (TAB_OFF + TAB_BYTES)           // 115200 (16B aligned)
#define RSEG_BYTES (KSEG * BM * 4)                // 32768
#define RBUF_BYTES (2 * RSEG_BYTES)               // 65536
#define WIS_OFF   (RBUF_OFF + RBUF_BYTES)
#define WIS_BYTES (BN * I_ * 4)                   // 2048
#define WOUT_OFF  (WIS_OFF + WIS_BYTES)
#define WOUT_BYTES (BN * O_ * 4)                  // 2048
#define OUTST_OFF (WOUT_OFF + WOUT_BYTES)
#define OUTST_BYTES (NWARP * BM * O_ * 4)         // 16384
#define SMEM_BYTES (OUTST_OFF + OUTST_BYTES)      // 201216

// ---------------- device scratch (no allocations) ----------------
__device__ float g_M[H_ * H_];                 // M[k][j] = relu(g[k])*effW[j][k]
__device__ int2  g_qlist[16 * JT_QCAP * 4];    // per-jtile interleaved quads [n][c]
__device__ int   g_qoff[16 * 64];              // per (jtile, group*4+seg) start quad
__device__ int   g_qcnt[16 * 64];              // per (jtile, group*4+seg) quad count (mult of 4)
__device__ float g_rA[H_ * B_];                // r buffers, TRANSPOSED [h][b]
__device__ float g_rB[H_ * B_];
__device__ float g_outp[2 * 16 * B_ * O_];     // per-jtile output partials, dbl buf
__device__ unsigned g_bar;

__device__ __forceinline__ float softplus_f(float v) {
    return fmaxf(v, 0.0f) + log1pf(expf(-fabsf(v)));
}

__device__ __forceinline__ void cp16(unsigned dst, const void* src) {
    asm volatile("cp.async.cg.shared.global [%0], [%1], 16;" :: "r"(dst), "l"(src));
}

// ---------------- setup kernel 0: build M (+ reset barrier) ----------------

__global__ void k_build_M(const float* __restrict__ wrec, const float* __restrict__ mwrec,
                          const float* __restrict__ refEI, const float* __restrict__ g) {
    int n = blockIdx.x * blockDim.x + threadIdx.x;   // n = j*H + k
    if (n == 0) g_bar = 0u;
    if (n >= H_ * H_) return;
    int j = n >> 10;
    int k = n & (H_ - 1);
    float ei = refEI[k];               // row 0 of refEI = ei (exactly +/-1)
    float w  = wrec[n];                // wrec[j][k]
    float e = fmaxf(w * ei, 0.0f) * ei * mwrec[n];   // effW[j][k]; (|ei|-1) term exactly 0
    g_M[k * H_ + j] = fmaxf(g[k], 0.0f) * e;
}

// ---------------- setup kernel 1: counts + prefix (single block, 1024 thr) ----

__global__ void k_setup_counts() {
    __shared__ int cnts[1024];
    int tid = threadIdx.x;                 // tid = gq*4 + s
    int gq = tid >> 2;
    int s  = tid & 3;
    int j0 = gq * 4;
    int c0 = 0, c1 = 0, c2 = 0, c3 = 0;
    for (int k = s * KSEG; k < (s + 1) * KSEG; ++k) {
        float4 v = *(const float4*)(g_M + (size_t)k * H_ + j0);
        c0 += (v.x != 0.0f); c1 += (v.y != 0.0f);
        c2 += (v.z != 0.0f); c3 += (v.w != 0.0f);
    }
    int mc = max(max(c0, c1), max(c2, c3));
    cnts[tid] = (mc + 3) & ~3;             // round to multiple of 4 (unroll-4 body)
    __syncthreads();
    if (tid < 16) {                        // per-jtile exclusive prefix over 64 slots
        int jt = tid, total = 0;
        for (int idx = 0; idx < 64; ++idx) {
            int c = cnts[jt * 64 + idx];
            if (total + c > JT_QCAP) c = (JT_QCAP - total) & ~3;   // defensive clamp
            g_qoff[jt * 64 + idx] = total;
            g_qcnt[jt * 64 + idx] = c;
            total += c;
        }
    }
}

// ---------------- setup kernel 2: fill lists + init r + out0/fill0 ----------

__global__ void k_setup_rest(const float* __restrict__ h0, const float* __restrict__ bvec,
                             const float* __restrict__ wout, float* __restrict__ out) {
    int blk = blockIdx.x;
    int tid = threadIdx.x;
    if (blk < 16) {
        // fill interleaved list for jtile = blk; thread = (g, s, c)
        int jt = blk;
        int c  = tid & 3;
        int s  = (tid >> 2) & 3;
        int g  = tid >> 4;                 // 0..15
        int j  = jt * BN + g * 4 + c;
        int slot = g * 4 + s;
        int base = g_qoff[jt * 64 + slot];
        int cnt  = g_qcnt[jt * 64 + slot];
        int2* dst = g_qlist + (size_t)jt * (JT_QCAP * 4);
        int n = 0;
        for (int k = 0; k < KSEG && n < cnt; ++k) {
            float v = g_M[(size_t)(s * KSEG + k) * H_ + j];
            if (v != 0.0f) {
                dst[(size_t)(base + n) * 4 + c] = make_int2(k * (BM * 4), __float_as_int(v));
                n++;
            }
        }
        for (; n < cnt; ++n)               // pad: +0.0*r[0] (exact no-op)
            dst[(size_t)(base + n) * 4 + c] = make_int2(0, 0);
    } else if (blk < 16 + 1024) {
        int n = (blk - 16) * 256 + tid;    // H*B, layout [h][b]
        int hh = n >> 8;
        g_rA[n] = softplus_f(h0[hh] + bvec[hh]);
    } else {
        // out0 + fill t=0 (single block of 256)
        __shared__ float ws[8][O_];
        __shared__ float o0[O_];
        float p[O_];
#pragma unroll
        for (int o = 0; o < O_; ++o) p[o] = 0.0f;
        for (int hh = tid; hh < H_; hh += 256) {
            float r0 = softplus_f(h0[hh] + bvec[hh]);
#pragma unroll
            for (int o = 0; o < O_; ++o) p[o] += r0 * wout[hh * O_ + o];
        }
#pragma unroll
        for (int d = 16; d > 0; d >>= 1)
#pragma unroll
            for (int o = 0; o < O_; ++o) p[o] += __shfl_xor_sync(0xffffffffu, p[o], d);
        if ((tid & 31) == 0)
            for (int o = 0; o < O_; ++o) ws[tid >> 5][o] = p[o];
        __syncthreads();
        if (tid < O_) {
            float sv = 0.0f;
            for (int w = 0; w < 8; ++w) sv += ws[w][tid];
            o0[tid] = sv;
        }
        __syncthreads();
        for (int rep = 0; rep < 8; ++rep) {
            int P = rep * 256 + tid;       // b*8 + o
            out[(size_t)(P >> 3) * (T_ * O_) + (P & 7)] = o0[P & 7];
        }
    }
}

// ---------------- persistent sparse RNN kernel ----------------

__global__ void __launch_bounds__(NTHR, 1)
k_rnn(const float* __restrict__ x, const float* __restrict__ noise,
      const float* __restrict__ wi, const float* __restrict__ wout,
      const float* __restrict__ bvec, const float* __restrict__ h0,
      float* __restrict__ out)
{
    extern __shared__ char smc[];
    int2*  sm_tab  = (int2*)(smc + TAB_OFF);
    float* sm_wis  = (float*)(smc + WIS_OFF);
    float* sm_wout = (float*)(smc + WOUT_OFF);
    float* sm_outst= (float*)(smc + OUTST_OFF);

    const int tid  = threadIdx.x;
    const int lane = tid & 31;
    const int w    = tid >> 5;              // warp = column group 0..15
    const int cta  = blockIdx.x;
    const int jtile = cta & 15;
    const int btile = cta >> 4;
    const int j0 = jtile * BN;
    const int b0 = btile * BM;
    const int jc0 = j0 + w * COLS_W;

    // ---- one-time staging ----
    {
        const int4* Lg = (const int4*)(g_qlist + (size_t)jtile * (JT_QCAP * 4));
        int4* Ls = (int4*)(smc + LIST_OFF);
        for (int n = tid; n < JT_QCAP * 2; n += NTHR) Ls[n] = __ldg(Lg + n);
        if (tid < 64)
            sm_tab[tid] = make_int2(g_qoff[jtile * 64 + tid], g_qcnt[jtile * 64 + tid]);
        {
            int c = tid >> 3, i = tid & 7;                   // 512 = 64*8
            sm_wis[tid]  = wi[i * H_ + j0 + c];
            sm_wout[tid] = wout[(size_t)j0 * O_ + tid];
        }
    }

    float bT[COLS_W], h[COLS_W];
#pragma unroll
    for (int cc = 0; cc < COLS_W; ++cc) {
        bT[cc] = bvec[jc0 + cc];
        h[cc]  = h0[jc0 + cc];
    }
    __syncthreads();

    const unsigned rs_sh = (unsigned)__cvta_generic_to_shared(smc + RBUF_OFF);
    unsigned epoch = 0;

    for (int t = 0; t < T_ - 1; ++t) {
        const float* __restrict__ Rg = (t & 1) ? g_rB : g_rA;
        float* __restrict__       Rn = (t & 1) ? g_rA : g_rB;

        // ---- prefetch segment 0 into buffer 0 ----
#pragma unroll
        for (int p = 0; p < 4; ++p) {
            int idx = p * NTHR + tid;                 // 2048 chunks of 16B
            int row = idx >> 3, piece = idx & 7;
            cp16(rs_sh + (unsigned)((row * BM + piece * 4) << 2),
                 Rg + (size_t)row * B_ + b0 + piece * 4);
        }
        asm volatile("cp.async.commit_group;" ::: "memory");

        // ---- prefetch noise & x (b = lane, this warp's 4 cols) ----
        float4 nz4 = __ldcg((const float4*)(noise + (size_t)(b0 + lane) * (T_ * H_)
                                            + (size_t)t * H_ + jc0));
        float4 xa  = __ldcg((const float4*)(x + (size_t)(b0 + lane) * (T_ * I_)
                                            + (size_t)t * I_));
        float4 xb  = __ldcg((const float4*)(x + (size_t)(b0 + lane) * (T_ * I_)
                                            + (size_t)t * I_ + 4));

        // ---- deterministic reduce of PREVIOUS step's output partials ----
        if (t >= 1 && tid < 16) {
            int P = cta * 16 + tid;                              // b*8+o
            const float* src = g_outp + (size_t)((t - 1) & 1) * (16 * B_ * O_);
            float s = 0.0f;
#pragma unroll
            for (int jt = 0; jt < 16; ++jt) s += __ldcv(src + jt * (B_ * O_) + P);
            out[(size_t)(P >> 3) * (T_ * O_) + (size_t)t * O_ + (P & 7)] = s;
        }

        float acc[COLS_W] = {0.f, 0.f, 0.f, 0.f};

        // ---- sparse GEMM over 4 k-segments ----
#pragma unroll 1
        for (int s = 0; s < NSEG; ++s) {
            asm volatile("cp.async.wait_group 0;" ::: "memory");
            __syncthreads();                 // segment s resident; buffer s-1 free
            if (s + 1 < NSEG) {
                const int nb = (s + 1) & 1;
                const int k0 = (s + 1) * KSEG;
#pragma unroll
                for (int p = 0; p < 4; ++p) {
                    int idx = p * NTHR + tid;
                    int row = idx >> 3, piece = idx & 7;
                    cp16(rs_sh + (unsigned)(nb * RSEG_BYTES) +
                         (unsigned)((row * BM + piece * 4) << 2),
                         Rg + (size_t)(k0 + row) * B_ + b0 + piece * 4);
                }
                asm volatile("cp.async.commit_group;" ::: "memory");
            }

            const char* rb = smc + RBUF_OFF + (s & 1) * RSEG_BYTES + lane * 4;
            const int2 tb = sm_tab[w * 4 + s];
            const int4* Lq = ((const int4*)(smc + LIST_OFF)) + tb.x * 2;
            const int cnt = tb.y;            // multiple of 4
            // unroll-4 straight-line body: 8 list loads + 16 gathers in flight
#pragma unroll 1
            for (int n = 0; n < cnt; n += 4) {
                int4 A0 = Lq[2 * n];     int4 B0 = Lq[2 * n + 1];
                int4 A1 = Lq[2 * n + 2]; int4 B1 = Lq[2 * n + 3];
                int4 A2 = Lq[2 * n + 4]; int4 B2 = Lq[2 * n + 5];
                int4 A3 = Lq[2 * n + 6]; int4 B3 = Lq[2 * n + 7];
                float r00 = *(const float*)(rb + A0.x), r01 = *(const float*)(rb + A0.z);
                float r02 = *(const float*)(rb + B0.x), r03 = *(const float*)(rb + B0.z);
                float r10 = *(const float*)(rb + A1.x), r11 = *(const float*)(rb + A1.z);
                float r12 = *(const float*)(rb + B1.x), r13 = *(const float*)(rb + B1.z);
                float r20 = *(const float*)(rb + A2.x), r21 = *(const float*)(rb + A2.z);
                float r22 = *(const float*)(rb + B2.x), r23 = *(const float*)(rb + B2.z);
                float r30 = *(const float*)(rb + A3.x), r31 = *(const float*)(rb + A3.z);
                float r32 = *(const float*)(rb + B3.x), r33 = *(const float*)(rb + B3.z);
                acc[0] += r00 * __int_as_float(A0.y);
                acc[1] += r01 * __int_as_float(A0.w);
                acc[2] += r02 * __int_as_float(B0.y);
                acc[3] += r03 * __int_as_float(B0.w);
                acc[0] += r10 * __int_as_float(A1.y);
                acc[1] += r11 * __int_as_float(A1.w);
                acc[2] += r12 * __int_as_float(B1.y);
                acc[3] += r13 * __int_as_float(B1.w);
                acc[0] += r20 * __int_as_float(A2.y);
                acc[1] += r21 * __int_as_float(A2.w);
                acc[2] += r22 * __int_as_float(B2.y);
                acc[3] += r23 * __int_as_float(B2.w);
                acc[0] += r30 * __int_as_float(A3.y);
                acc[1] += r31 * __int_as_float(A3.w);
                acc[2] += r32 * __int_as_float(B3.y);
                acc[3] += r33 * __int_as_float(B3.w);
            }
        }

        // ---- input projection ----
        float inp[COLS_W];
#pragma unroll
        for (int cc = 0; cc < COLS_W; ++cc) {
            const float* wv = sm_wis + (w * COLS_W + cc) * I_;
            float4 wA = *(const float4*)wv;
            float4 wB = *(const float4*)(wv + 4);
            inp[cc] = xa.x * wA.x + xa.y * wA.y + xa.z * wA.z + xa.w * wA.w
                    + xb.x * wB.x + xb.y * wB.y + xb.z * wB.z + xb.w * wB.w;
        }

        float nzv[COLS_W] = {nz4.x, nz4.y, nz4.z, nz4.w};

        // ---- state update + softplus + r write ----
        float rn[COLS_W];
#pragma unroll
        for (int cc = 0; cc < COLS_W; ++cc) {
            float hv = h[cc];
            hv = hv + NSTD_ * nzv[cc] + ALPHA_ * (-hv + acc[cc] + inp[cc]);
            h[cc] = hv;
            float rv = softplus_f(hv + bT[cc]);
            rn[cc] = rv;
            Rn[(size_t)(jc0 + cc) * B_ + b0 + lane] = rv;   // coalesced 128B per column
        }

        // ---- output partials over this warp's 4 columns ----
        float p[O_];
#pragma unroll
        for (int o = 0; o < O_; ++o) p[o] = 0.0f;
#pragma unroll
        for (int cc = 0; cc < COLS_W; ++cc) {
            const float* wv = sm_wout + (w * COLS_W + cc) * O_;
            float4 wo0 = *(const float4*)wv;
            float4 wo1 = *(const float4*)(wv + 4);
            float rv = rn[cc];
            p[0] += rv * wo0.x; p[1] += rv * wo0.y; p[2] += rv * wo0.z; p[3] += rv * wo0.w;
            p[4] += rv * wo1.x; p[5] += rv * wo1.y; p[6] += rv * wo1.z; p[7] += rv * wo1.w;
        }
        {
            float4* st = (float4*)(sm_outst + ((size_t)w * BM + lane) * O_);
            st[0] = make_float4(p[0], p[1], p[2], p[3]);
            st[1] = make_float4(p[4], p[5], p[6], p[7]);
        }
        __syncthreads();
        if (tid < 256) {
            int brel = tid >> 3, o = tid & 7;       // 32 b x 8 o
            float ssum = 0.0f;
#pragma unroll
            for (int ww = 0; ww < NWARP; ++ww)
                ssum += sm_outst[((size_t)ww * BM + brel) * O_ + o];
            g_outp[(size_t)(t & 1) * (16 * B_ * O_) + (size_t)jtile * (B_ * O_)
                   + (size_t)(b0 + brel) * O_ + o] = ssum;
        }

        // ---- grid barrier (busy poll; only thread 0 spins) ----
        epoch++;
        __syncthreads();
        if (tid == 0) {
            __threadfence();
            atomicAdd(&g_bar, 1u);
            const unsigned target = epoch * GRID_;
            while (*(volatile unsigned*)&g_bar < target) { }
        }
        __syncthreads();
    }

    // ---- final output reduce (step T-2 -> out[:, T-1, :]) ----
    if (tid < 16) {
        int P = cta * 16 + tid;
        const float* src = g_outp + (size_t)((T_ - 2) & 1) * (16 * B_ * O_);
        float s = 0.0f;
#pragma unroll
        for (int jt = 0; jt < 16; ++jt) s += __ldcv(src + jt * (B_ * O_) + P);
        out[(size_t)(P >> 3) * (T_ * O_) + (size_t)(T_ - 1) * O_ + (P & 7)] = s;
    }
}

// ---------------- launch (k_rnn at launch index 3) ----------------

extern "C" void kernel_launch(void* const* d_in, const int* in_sizes, int n_in,
                              void* d_out, int out_size) {
    const float* x     = (const float*)d_in[0];
    const float* noise = (const float*)d_in[1];
    const float* wi    = (const float*)d_in[2];
    const float* wrec  = (const float*)d_in[3];
    const float* wout  = (const float*)d_in[4];
    const float* bvec  = (const float*)d_in[5];
    const float* g     = (const float*)d_in[6];
    const float* h0    = (const float*)d_in[7];
    const float* refEI = (const float*)d_in[8];
    const float* mwrec = (const float*)d_in[9];
    float* out = (float*)d_out;

    cudaFuncSetAttribute(k_rnn, cudaFuncAttributeMaxDynamicSharedMemorySize, SMEM_BYTES);

    k_build_M<<<(H_ * H_ + 255) / 256, 256>>>(wrec, mwrec, refEI, g);
    k_setup_counts<<<1, 1024>>>();
    k_setup_rest<<<16 + 1024 + 1, 256>>>(h0, bvec, wout, out);
    k_rnn<<<GRID_, NTHR, SMEM_BYTES>>>(x, noise, wi, wout, bvec, h0, out);
}